// round 12
// baseline (speedup 1.0000x reference)
#include <cuda_runtime.h>
#include <cuda_bf16.h>

// EMA: y[n] = w*x[n] + (1-w)*y[n-1], scan over last (contiguous) axis.
// Shapes: input (16,8,256,2048) f32, initial_state (16,8,256), weight (8,256).
// One warp per series (32768 series), constant-decay B-only Kogge-Stone scan.
// R12: ILP-4 chunk grouping — 4 independent 5-deep shuffle chains per 512
// frames (chain latency per byte halves vs R10's ILP-2), each chunk's store
// issued right after its own recurrence (R10 mechanism), next-iteration carry
// resolved before any stores. Depth-2 pipeline over 512-frame groups.

#define N_FRAMES 2048
#define SERIES_PER_WB 2048   /* N_RES * N_BINS = 8*256 */
#define N_SERIES 32768       /* 16*8*256 */

__global__ __launch_bounds__(256, 4)
void ema_scan_kernel(const float* __restrict__ x,
                     const float* __restrict__ init_state,
                     const float* __restrict__ weight,
                     float* __restrict__ y) {
    const int warp_global = (blockIdx.x * blockDim.x + threadIdx.x) >> 5;
    const int lane = threadIdx.x & 31;
    if (warp_global >= N_SERIES) return;

    const int series = warp_global;

    // weight index = series % (N_RES*N_BINS); clamp to [0,1]
    const float w_raw = weight[series & (SERIES_PER_WB - 1)];
    const float w   = fminf(fmaxf(w_raw, 0.0f), 1.0f);
    const float omw = 1.0f - w;

    // Powers of the 4-element decay: P[k] = omw^(4*2^k)
    const float P1  = ((omw * omw) * (omw * omw));  // omw^4
    const float P2  = P1 * P1;                      // omw^8
    const float P4  = P2 * P2;                      // omw^16
    const float P8  = P4 * P4;                      // omw^32
    const float P16 = P8 * P8;                      // omw^64
    const float P32 = P16 * P16;                    // omw^128 (full-chunk decay)

    // Apow = omw^(4*lane): carry multiplier for this lane's exclusive state.
    float Apow = 1.0f;
    if (lane & 1)  Apow *= P1;
    if (lane & 2)  Apow *= P2;
    if (lane & 4)  Apow *= P4;
    if (lane & 8)  Apow *= P8;
    if (lane & 16) Apow *= P16;

    float carry = init_state[series];

    const float4* __restrict__ xin  =
        reinterpret_cast<const float4*>(x + (size_t)series * N_FRAMES);
    float4* __restrict__ yout =
        reinterpret_cast<float4*>(y + (size_t)series * N_FRAMES);

    // Depth-2 pipeline over groups of 4 chunks (512 frames).
    float4 v0 = __ldcs(&xin[lane]);
    float4 v1 = __ldcs(&xin[32 + lane]);
    float4 v2 = __ldcs(&xin[64 + lane]);
    float4 v3 = __ldcs(&xin[96 + lane]);

    #pragma unroll
    for (int t = 0; t < N_FRAMES / 512; ++t) {
        float4 n0, n1, n2, n3;
        if (t < N_FRAMES / 512 - 1) {
            n0 = __ldcs(&xin[(t + 1) * 128 + lane]);
            n1 = __ldcs(&xin[(t + 1) * 128 + 32 + lane]);
            n2 = __ldcs(&xin[(t + 1) * 128 + 64 + lane]);
            n3 = __ldcs(&xin[(t + 1) * 128 + 96 + lane]);
        }

        // Local composites (4 independent).
        float B0 = w * v0.x;
        B0 = fmaf(omw, B0, w * v0.y);
        B0 = fmaf(omw, B0, w * v0.z);
        B0 = fmaf(omw, B0, w * v0.w);

        float B1 = w * v1.x;
        B1 = fmaf(omw, B1, w * v1.y);
        B1 = fmaf(omw, B1, w * v1.z);
        B1 = fmaf(omw, B1, w * v1.w);

        float B2 = w * v2.x;
        B2 = fmaf(omw, B2, w * v2.y);
        B2 = fmaf(omw, B2, w * v2.z);
        B2 = fmaf(omw, B2, w * v2.w);

        float B3 = w * v3.x;
        B3 = fmaf(omw, B3, w * v3.y);
        B3 = fmaf(omw, B3, w * v3.z);
        B3 = fmaf(omw, B3, w * v3.w);

        // Four independent Kogge-Stone B-scans, interleaved for ILP.
        float Bu0, Bu1, Bu2, Bu3;
        Bu0 = __shfl_up_sync(0xFFFFFFFFu, B0, 1);
        Bu1 = __shfl_up_sync(0xFFFFFFFFu, B1, 1);
        Bu2 = __shfl_up_sync(0xFFFFFFFFu, B2, 1);
        Bu3 = __shfl_up_sync(0xFFFFFFFFu, B3, 1);
        if (lane >= 1)  { B0 = fmaf(P1,  Bu0, B0); B1 = fmaf(P1,  Bu1, B1);
                          B2 = fmaf(P1,  Bu2, B2); B3 = fmaf(P1,  Bu3, B3); }
        Bu0 = __shfl_up_sync(0xFFFFFFFFu, B0, 2);
        Bu1 = __shfl_up_sync(0xFFFFFFFFu, B1, 2);
        Bu2 = __shfl_up_sync(0xFFFFFFFFu, B2, 2);
        Bu3 = __shfl_up_sync(0xFFFFFFFFu, B3, 2);
        if (lane >= 2)  { B0 = fmaf(P2,  Bu0, B0); B1 = fmaf(P2,  Bu1, B1);
                          B2 = fmaf(P2,  Bu2, B2); B3 = fmaf(P2,  Bu3, B3); }
        Bu0 = __shfl_up_sync(0xFFFFFFFFu, B0, 4);
        Bu1 = __shfl_up_sync(0xFFFFFFFFu, B1, 4);
        Bu2 = __shfl_up_sync(0xFFFFFFFFu, B2, 4);
        Bu3 = __shfl_up_sync(0xFFFFFFFFu, B3, 4);
        if (lane >= 4)  { B0 = fmaf(P4,  Bu0, B0); B1 = fmaf(P4,  Bu1, B1);
                          B2 = fmaf(P4,  Bu2, B2); B3 = fmaf(P4,  Bu3, B3); }
        Bu0 = __shfl_up_sync(0xFFFFFFFFu, B0, 8);
        Bu1 = __shfl_up_sync(0xFFFFFFFFu, B1, 8);
        Bu2 = __shfl_up_sync(0xFFFFFFFFu, B2, 8);
        Bu3 = __shfl_up_sync(0xFFFFFFFFu, B3, 8);
        if (lane >= 8)  { B0 = fmaf(P8,  Bu0, B0); B1 = fmaf(P8,  Bu1, B1);
                          B2 = fmaf(P8,  Bu2, B2); B3 = fmaf(P8,  Bu3, B3); }
        Bu0 = __shfl_up_sync(0xFFFFFFFFu, B0, 16);
        Bu1 = __shfl_up_sync(0xFFFFFFFFu, B1, 16);
        Bu2 = __shfl_up_sync(0xFFFFFFFFu, B2, 16);
        Bu3 = __shfl_up_sync(0xFFFFFFFFu, B3, 16);
        if (lane >= 16) { B0 = fmaf(P16, Bu0, B0); B1 = fmaf(P16, Bu1, B1);
                          B2 = fmaf(P16, Bu2, B2); B3 = fmaf(P16, Bu3, B3); }

        // Exclusive prefixes and chunk totals.
        float B0e = __shfl_up_sync(0xFFFFFFFFu, B0, 1);
        float B1e = __shfl_up_sync(0xFFFFFFFFu, B1, 1);
        float B2e = __shfl_up_sync(0xFFFFFFFFu, B2, 1);
        float B3e = __shfl_up_sync(0xFFFFFFFFu, B3, 1);
        float T0  = __shfl_sync(0xFFFFFFFFu, B0, 31);
        float T1  = __shfl_sync(0xFFFFFFFFu, B1, 31);
        float T2  = __shfl_sync(0xFFFFFFFFu, B2, 31);
        float T3  = __shfl_sync(0xFFFFFFFFu, B3, 31);

        // Incoming states; next-iteration carry resolved before any stores.
        float y_in0  = fmaf(Apow, carry, (lane == 0) ? 0.0f : B0e);
        float state1 = fmaf(P32, carry, T0);
        float y_in1  = fmaf(Apow, state1, (lane == 0) ? 0.0f : B1e);
        float state2 = fmaf(P32, state1, T1);
        float y_in2  = fmaf(Apow, state2, (lane == 0) ? 0.0f : B2e);
        float state3 = fmaf(P32, state2, T2);
        float y_in3  = fmaf(Apow, state3, (lane == 0) ? 0.0f : B3e);
        carry        = fmaf(P32, state3, T3);

        // Per-chunk recurrence + immediate store (stores drain while the next
        // chunk's dependent chain computes).
        {
            float a0 = fmaf(omw, y_in0, w * v0.x);
            float a1 = fmaf(omw, a0,    w * v0.y);
            float a2 = fmaf(omw, a1,    w * v0.z);
            float a3 = fmaf(omw, a2,    w * v0.w);
            __stcs(&yout[t * 128 + lane], make_float4(a0, a1, a2, a3));
        }
        {
            float a0 = fmaf(omw, y_in1, w * v1.x);
            float a1 = fmaf(omw, a0,    w * v1.y);
            float a2 = fmaf(omw, a1,    w * v1.z);
            float a3 = fmaf(omw, a2,    w * v1.w);
            __stcs(&yout[t * 128 + 32 + lane], make_float4(a0, a1, a2, a3));
        }
        {
            float a0 = fmaf(omw, y_in2, w * v2.x);
            float a1 = fmaf(omw, a0,    w * v2.y);
            float a2 = fmaf(omw, a1,    w * v2.z);
            float a3 = fmaf(omw, a2,    w * v2.w);
            __stcs(&yout[t * 128 + 64 + lane], make_float4(a0, a1, a2, a3));
        }
        {
            float a0 = fmaf(omw, y_in3, w * v3.x);
            float a1 = fmaf(omw, a0,    w * v3.y);
            float a2 = fmaf(omw, a1,    w * v3.z);
            float a3 = fmaf(omw, a2,    w * v3.w);
            __stcs(&yout[t * 128 + 96 + lane], make_float4(a0, a1, a2, a3));
        }

        v0 = n0; v1 = n1; v2 = n2; v3 = n3;
    }
}

extern "C" void kernel_launch(void* const* d_in, const int* in_sizes, int n_in,
                              void* d_out, int out_size) {
    const float* x    = (const float*)d_in[0];   // input (16,8,256,2048)
    const float* init = (const float*)d_in[1];   // initial_state (16,8,256)
    const float* wgt  = (const float*)d_in[2];   // weight (8,256)
    float* y = (float*)d_out;

    // 32768 warps, 8 warps (256 threads) per block -> 4096 blocks.
    const int threads = 256;
    const int blocks = (N_SERIES * 32) / threads;
    ema_scan_kernel<<<blocks, threads>>>(x, init, wgt, y);
}